// round 17
// baseline (speedup 1.0000x reference)
#include <cuda_runtime.h>
#include <cuda_fp16.h>
#include <cstdint>

#define D 128
#define N0MAX 100000
#define NALL  (100000 + 150000 + 80000)
#define EALL  3000000
#define SCAN_CHUNK 4096
#define SCAN_BLOCKS ((N0MAX + SCAN_CHUNK - 1) / SCAN_CHUNK)

typedef unsigned long long ull;
typedef unsigned int u32;

// ---------------- static scratch (allocation-free rule) ----------------
__device__ __half g_gall[(size_t)NALL * 128];   // fp16 projected features, concat [g0|g1|g2]
__device__ float g_a2all[NALL];                 // concat [a2_0|a2_1|a2_2]
__device__ float g_a1_0[N0MAX];
// prepped weights: 5 matrices (W1, Wagg0..3) x 32KB fp16 tiles (hi plane only used),
// transposed to [n][k], 16B-chunk XOR-swizzled (ldmatrix-ready, raw smem copy)
__device__ unsigned char g_wprep[5 * 2 * 32768];
// combined CSR scratch
__device__ int g_cnt[N0MAX + 1];
__device__ int g_off[N0MAX + 1];
__device__ int g_cur[N0MAX];
__device__ int2 g_sedge[EALL];                  // {col, sigmoid-weight bits} per binned edge
__device__ int g_bsum[SCAN_BLOCKS + 1];

__device__ __forceinline__ u32 smem_to_u32(const void* p) {
    u32 a;
    asm("{ .reg .u64 t; cvta.to.shared.u64 t, %1; cvt.u32.u64 %0, t; }" : "=r"(a) : "l"(p));
    return a;
}

// byte offset of 16B chunk (row, kc) in a 128x128 fp16 tile (256B rows),
// XOR swizzle on chunk index by row&7 -> conflict-free ldmatrix + staging
#define CH(row, kc) ((u32)((row) * 256 + ((((kc)) ^ ((row) & 7)) << 4)))

// pack 8 fp32 -> fp16 uint4
__device__ __forceinline__ uint4 pack8h(const float* v) {
    u32 hw[4];
#pragma unroll
    for (int j = 0; j < 4; j++) {
        __half2 hh = __floats2half2_rn(v[2 * j], v[2 * j + 1]);
        hw[j] = *(u32*)&hh;
    }
    return make_uint4(hw[0], hw[1], hw[2], hw[3]);
}

// ---------------- weight prep: transpose + fp16 + swizzle (40 blocks) ----------
__global__ void prep_w(const float* __restrict__ W1, const float* __restrict__ Wagg,
                       unsigned char* __restrict__ wp) {
    int m = blockIdx.x >> 3, it = blockIdx.x & 7, tid = threadIdx.x;
    unsigned char* hip = wp + (size_t)m * 2 * 32768;
    int f = it * 256 + tid;               // chunk id 0..2047
    int n = f >> 4, kc = f & 15, k0 = kc * 8;
    float v[8];
#pragma unroll
    for (int j = 0; j < 8; j++) {
        int k = k0 + j;
        v[j] = (m == 0) ? W1[k * 128 + n] : Wagg[((m - 1) * 128 + k) * 128 + n];
    }
    *(uint4*)(hip + CH(n, kc)) = pack8h(v);
}

// ---------------- node kernel (mma.sync m16n8k16 fp16, single pass, merged) --
// smem: A (fp16) | W (fp16) | header  => 68KB, 2 CTAs/SM
#define OFF_A    0
#define OFF_W    32768
#define OFF_HDR  65536
#define SMEM_REQ (65536 + 3072 + 1024)

__device__ __forceinline__ void copy32k(void* dst, const void* src, int tid) {
    const uint4* s = (const uint4*)src;
    uint4* d = (uint4*)dst;
#pragma unroll
    for (int i = 0; i < 8; i++) d[tid + i * 256] = s[tid + i * 256];
}

// full K=128 (8 k-steps) of the 128x128 GEMM for this warp
__device__ __forceinline__ void gemm_pass(u32 Ab, u32 Wb, int r0, int cbase, int lane,
                                          float c[2][8][4]) {
    const int q = lane >> 3, sr = lane & 7;
#pragma unroll
    for (int mt = 0; mt < 2; mt++)
#pragma unroll
        for (int nt = 0; nt < 8; nt++)
#pragma unroll
            for (int j = 0; j < 4; j++) c[mt][nt][j] = 0.f;
#pragma unroll 1
    for (int ks = 0; ks < 8; ks++) {
        u32 a[2][4];
#pragma unroll
        for (int mt = 0; mt < 2; mt++) {
            int row = r0 + mt * 16 + ((q & 1) << 3) + sr;
            int kc = 2 * ks + (q >> 1);
            u32 ad = Ab + CH(row, kc);
            asm volatile("ldmatrix.sync.aligned.m8n8.x4.shared.b16 {%0,%1,%2,%3}, [%4];"
                         : "=r"(a[mt][0]), "=r"(a[mt][1]), "=r"(a[mt][2]), "=r"(a[mt][3])
                         : "r"(ad));
        }
        u32 b[8][2];
#pragma unroll
        for (int nb = 0; nb < 4; nb++) {
            int rown = cbase + nb * 16 + ((q >> 1) << 3) + sr;
            int kc = 2 * ks + (q & 1);
            u32 ad = Wb + CH(rown, kc);
            asm volatile("ldmatrix.sync.aligned.m8n8.x4.shared.b16 {%0,%1,%2,%3}, [%4];"
                         : "=r"(b[2 * nb][0]), "=r"(b[2 * nb][1]),
                           "=r"(b[2 * nb + 1][0]), "=r"(b[2 * nb + 1][1])
                         : "r"(ad));
        }
#pragma unroll
        for (int mt = 0; mt < 2; mt++)
#pragma unroll
            for (int nt = 0; nt < 8; nt++)
                asm volatile("mma.sync.aligned.m16n8k16.row.col.f32.f16.f16.f32 "
                             "{%0,%1,%2,%3}, {%4,%5,%6,%7}, {%8,%9}, {%0,%1,%2,%3};"
                             : "+f"(c[mt][nt][0]), "+f"(c[mt][nt][1]),
                               "+f"(c[mt][nt][2]), "+f"(c[mt][nt][3])
                             : "r"(a[mt][0]), "r"(a[mt][1]), "r"(a[mt][2]), "r"(a[mt][3]),
                               "r"(b[nt][0]), "r"(b[nt][1]));
    }
}

__global__ __launch_bounds__(256, 2)
void node_all(const float* __restrict__ x0, const float* __restrict__ x1,
              const float* __restrict__ x2,
              int N0, int N1, int N2, int NB0, int NB1, int boff,
              const unsigned char* __restrict__ w1p,
              const unsigned char* __restrict__ wg0p,
              const unsigned char* __restrict__ wg1p,
              const unsigned char* __restrict__ wg2p,
              const unsigned char* __restrict__ wsp,
              const float* __restrict__ b1,
              const float* __restrict__ a1w, const float* __restrict__ a1bp,
              const float* __restrict__ a2w, const float* __restrict__ a2bp,
              const float* __restrict__ bagg,
              __half* __restrict__ gall, float* __restrict__ a1out,
              float* __restrict__ a2all, float* __restrict__ selfout) {
    extern __shared__ char sraw[];
    const u32 sb = smem_to_u32(sraw);
    const u32 base = (sb + 1023u) & ~1023u;
    char* bp = sraw + (base - sb);
    float* sBB  = (float*)(bp + OFF_HDR);
    float* sAW1 = sBB + 128;
    float* sAW2 = sAW1 + 128;
    float* sBG  = sAW2 + 128;
    float* sPA1 = sBG + 128;
    float* sPA2 = sPA1 + 128;

    // dataset select by (offset) block id
    int b = blockIdx.x + boff;
    const float* x;
    const unsigned char* wgh;
    int nrows, goff, tile;
    bool ds0 = false;
    if (b < NB0) {
        x = x0; nrows = N0; goff = 0; wgh = wg0p; tile = b; ds0 = true;
    } else if (b < NB0 + NB1) {
        x = x1; nrows = N1; goff = N0; wgh = wg1p; tile = b - NB0;
    } else {
        x = x2; nrows = N2; goff = N0 + N1; wgh = wg2p; tile = b - NB0 - NB1;
    }
    __half* gout = gall + (size_t)goff * D;
    float* a2out = a2all + goff;
    const int rbase = tile * 128;

    const int tid = threadIdx.x, wid = tid >> 5, lane = tid & 31;
    const int wm = wid & 3, wn = wid >> 2;
    const int r0 = wm * 32, cbase = wn * 64;
    const u32 sA = base + OFF_A;
    const u32 sW = base + OFF_W;

    if (tid < 128) {
        sBB[tid] = b1[tid];
        sAW1[tid] = a1w[tid];
        sAW2[tid] = a2w[tid];
        sBG[tid] = bagg[tid];
    }
    copy32k(bp + OFF_W, w1p, tid);
#pragma unroll 1
    for (int it = 0; it < 8; it++) {
        int f = tid + it * 256;
        int row = f >> 4, kc = f & 15;
        float v[8];
        if (rbase + row < nrows) {
            const float4* xp = (const float4*)(x + (size_t)(rbase + row) * 128 + kc * 8);
            float4 p0 = xp[0], p1 = xp[1];
            v[0] = p0.x; v[1] = p0.y; v[2] = p0.z; v[3] = p0.w;
            v[4] = p1.x; v[5] = p1.y; v[6] = p1.z; v[7] = p1.w;
        } else {
#pragma unroll
            for (int j = 0; j < 8; j++) v[j] = 0.f;
        }
        *(uint4*)(bp + OFF_A + CH(row, kc)) = pack8h(v);
    }
    __syncthreads();

    float c[2][8][4];
    float pph1[4], pph2[4];

    // ---- GEMM1: h = x @ W1^T ----
    gemm_pass(sA, sW, r0, cbase, lane, c);
    __syncthreads();   // all warps done reading sA(x)/sW before overwrite

    // epilogue 1: bias+relu, attention dots, h -> sA fp16
#pragma unroll
    for (int mt = 0; mt < 2; mt++)
#pragma unroll
        for (int half = 0; half < 2; half++) {
            int row = r0 + mt * 16 + half * 8 + (lane >> 2);
            float ph1 = 0.f, ph2 = 0.f;
#pragma unroll
            for (int nt = 0; nt < 8; nt++) {
                int col = cbase + nt * 8 + 2 * (lane & 3);
                float h0 = fmaxf(c[mt][nt][half * 2 + 0] + sBB[col], 0.f);
                float h1 = fmaxf(c[mt][nt][half * 2 + 1] + sBB[col + 1], 0.f);
                ph1 += h0 * sAW1[col] + h1 * sAW1[col + 1];
                ph2 += h0 * sAW2[col] + h1 * sAW2[col + 1];
                __half2 hhi = __floats2half2_rn(h0, h1);
                u32 ao = (u32)(row * 256 + (((col >> 3) ^ (row & 7)) << 4) + (col & 7) * 2);
                *(u32*)(bp + OFF_A + ao) = *(u32*)&hhi;
            }
            ph1 += __shfl_xor_sync(0xffffffffu, ph1, 1);
            ph1 += __shfl_xor_sync(0xffffffffu, ph1, 2);
            ph2 += __shfl_xor_sync(0xffffffffu, ph2, 1);
            ph2 += __shfl_xor_sync(0xffffffffu, ph2, 2);
            pph1[mt * 2 + half] = ph1;
            pph2[mt * 2 + half] = ph2;
            if (wn == 0 && (lane & 3) == 0) {
                sPA1[row] = ph1;
                sPA2[row] = ph2;
            }
        }
    copy32k(bp + OFF_W, wgh, tid);   // stage Wg (safe: post-GEMM1 barrier above)
    __syncthreads();
    if (wn == 1 && (lane & 3) == 0) {
        const float a1b = *a1bp, a2b = *a2bp;
#pragma unroll
        for (int mt = 0; mt < 2; mt++)
#pragma unroll
            for (int half = 0; half < 2; half++) {
                int row = r0 + mt * 16 + half * 8 + (lane >> 2);
                int grow = rbase + row;
                if (grow < nrows) {
                    if (ds0) a1out[grow] = sPA1[row] + pph1[mt * 2 + half] + a1b;
                    a2out[grow] = sPA2[row] + pph2[mt * 2 + half] + a2b;
                }
            }
    }

    // ---- GEMM2: g = h @ Wg^T -> fp16 global ----
    gemm_pass(sA, sW, r0, cbase, lane, c);
#pragma unroll
    for (int mt = 0; mt < 2; mt++)
#pragma unroll
        for (int half = 0; half < 2; half++) {
            int row = r0 + mt * 16 + half * 8 + (lane >> 2);
            int grow = rbase + row;
            if (grow < nrows) {
#pragma unroll
                for (int nt = 0; nt < 8; nt++) {
                    int col = cbase + nt * 8 + 2 * (lane & 3);
                    __half2 hv = __floats2half2_rn(c[mt][nt][half * 2 + 0],
                                                   c[mt][nt][half * 2 + 1]);
                    *(u32*)(gout + (size_t)grow * D + col) = *(u32*)&hv;
                }
            }
        }

    // ---- GEMM3 (x0 only): self = h @ Wself^T + bagg -> out ----
    if (ds0) {
        __syncthreads();   // all warps done reading sW(Wg)
        copy32k(bp + OFF_W, wsp, tid);
        __syncthreads();
        gemm_pass(sA, sW, r0, cbase, lane, c);
#pragma unroll
        for (int mt = 0; mt < 2; mt++)
#pragma unroll
            for (int half = 0; half < 2; half++) {
                int row = r0 + mt * 16 + half * 8 + (lane >> 2);
                int grow = rbase + row;
                if (grow < nrows) {
#pragma unroll
                    for (int nt = 0; nt < 8; nt++) {
                        int col = cbase + nt * 8 + 2 * (lane & 3);
                        float2 v = make_float2(c[mt][nt][half * 2 + 0] + sBG[col],
                                               c[mt][nt][half * 2 + 1] + sBG[col + 1]);
                        *(float2*)(selfout + (size_t)grow * D + col) = v;
                    }
                }
            }
    }
}

// ---------------- binning kernels (combined CSR over all 3 lists) ----------------
__global__ void zero_kernel(int* p, int n) {
    int i = blockIdx.x * blockDim.x + threadIdx.x;
    if (i < n) p[i] = 0;
}

__global__ void hist_kernel(const int* __restrict__ r0, int E0,
                            const int* __restrict__ r1, int E1,
                            const int* __restrict__ r2, int E2,
                            int* __restrict__ cnt) {
    int t = blockIdx.x * blockDim.x + threadIdx.x;
    int row;
    if (t < E0) row = __ldg(r0 + t);
    else if ((t -= E0) < E1) row = __ldg(r1 + t);
    else if ((t -= E1) < E2) row = __ldg(r2 + t);
    else return;
    atomicAdd(&cnt[row], 1);
}

// ---- parallel scan phase A: per-block sums of 4096-element chunks ----
__global__ __launch_bounds__(1024)
void scanA_kernel(const int* __restrict__ cnt, int n, int* __restrict__ bsum) {
    __shared__ int wsum[32];
    const int tid = threadIdx.x, lane = tid & 31, wid = tid >> 5;
    int idx = blockIdx.x * SCAN_CHUNK + tid * 4;
    int s = 0;
#pragma unroll
    for (int j = 0; j < 4; j++) s += (idx + j < n) ? cnt[idx + j] : 0;
#pragma unroll
    for (int off = 16; off >= 1; off >>= 1) s += __shfl_down_sync(0xffffffffu, s, off);
    if (lane == 0) wsum[wid] = s;
    __syncthreads();
    if (wid == 0) {
        int y = wsum[lane];
#pragma unroll
        for (int off = 16; off >= 1; off >>= 1) y += __shfl_down_sync(0xffffffffu, y, off);
        if (lane == 0) bsum[blockIdx.x] = y;
    }
}

// ---- phase C: per-block exclusive scan; block offset self-computed from bsum ----
__global__ __launch_bounds__(1024)
void scanC_kernel(const int* __restrict__ cnt, int n, int nb,
                  const int* __restrict__ bsum,
                  int* __restrict__ offs, int* __restrict__ cur) {
    __shared__ int wsum[32];
    __shared__ int s_boff, s_total;
    const int tid = threadIdx.x, lane = tid & 31, wid = tid >> 5;
    if (wid == 0) {
        int v = (lane < nb) ? bsum[lane] : 0;            // nb <= 25 < 32
        int pre = (lane < blockIdx.x) ? v : 0;
        int tot = v;
#pragma unroll
        for (int off = 16; off >= 1; off >>= 1) {
            pre += __shfl_down_sync(0xffffffffu, pre, off);
            tot += __shfl_down_sync(0xffffffffu, tot, off);
        }
        if (lane == 0) { s_boff = pre; s_total = tot; }
    }
    int idx = blockIdx.x * SCAN_CHUNK + tid * 4;
    int v[4];
#pragma unroll
    for (int j = 0; j < 4; j++) v[j] = (idx + j < n) ? cnt[idx + j] : 0;
    int tsum = v[0] + v[1] + v[2] + v[3];
    int xv = tsum;
#pragma unroll
    for (int off = 1; off < 32; off <<= 1) {
        int t = __shfl_up_sync(0xffffffffu, xv, off);
        if (lane >= off) xv += t;
    }
    if (lane == 31) wsum[wid] = xv;
    __syncthreads();
    if (wid == 0) {
        int y = wsum[lane];
#pragma unroll
        for (int off = 1; off < 32; off <<= 1) {
            int t = __shfl_up_sync(0xffffffffu, y, off);
            if (lane >= off) y += t;
        }
        wsum[lane] = y;
    }
    __syncthreads();
    int warpoff = (wid == 0) ? 0 : wsum[wid - 1];
    int excl = s_boff + warpoff + xv - tsum;
#pragma unroll
    for (int j = 0; j < 4; j++) {
        if (idx + j < n) { offs[idx + j] = excl; cur[idx + j] = excl; }
        excl += v[j];
    }
    if (blockIdx.x == 0 && tid == 0) offs[n] = s_total;
}

// ---- scat: bin edge + fuse sigmoid weight (list subset per call) ----
__device__ __forceinline__ float fsig(float s) {
    return 1.0f / (1.0f + __expf(-s));
}

__global__ void scat_kernel(const int* __restrict__ r0, const int* __restrict__ c0, int E0,
                            const int* __restrict__ r1, const int* __restrict__ c1, int E1,
                            const int* __restrict__ r2, const int* __restrict__ c2, int E2,
                            int base1, int base2,
                            const float* __restrict__ a1, const float* __restrict__ a2,
                            int* __restrict__ cur, int2* __restrict__ sedge) {
    int t = blockIdx.x * blockDim.x + threadIdx.x;
    int row, col;
    if (t < E0) { row = __ldg(r0 + t); col = __ldg(c0 + t); }
    else if ((t -= E0) < E1) { row = __ldg(r1 + t); col = __ldg(c1 + t) + base1; }
    else if ((t -= E1) < E2) { row = __ldg(r2 + t); col = __ldg(c2 + t) + base2; }
    else return;
    float s = fsig(__ldg(a1 + row) + __ldg(a2 + col));
    int p = atomicAdd(&cur[row], 1);
    sedge[p] = make_int2(col, __float_as_int(s));
}

// ---------------- aggregate: one warp per row, half-warp per edge ----------------
// half-warp lane hl (0-15) accumulates cols hl*8..hl*8+7 for edge c
__device__ __forceinline__ void gacc16(int c, float sv, int hl,
                                       const __half* __restrict__ g, float acc[8]) {
    uint4 u = __ldg((const uint4*)(g + (size_t)c * D) + hl);
    float2 f0 = __half22float2(*reinterpret_cast<__half2*>(&u.x));
    float2 f1 = __half22float2(*reinterpret_cast<__half2*>(&u.y));
    float2 f2 = __half22float2(*reinterpret_cast<__half2*>(&u.z));
    float2 f3 = __half22float2(*reinterpret_cast<__half2*>(&u.w));
    acc[0] += sv * f0.x; acc[1] += sv * f0.y;
    acc[2] += sv * f1.x; acc[3] += sv * f1.y;
    acc[4] += sv * f2.x; acc[5] += sv * f2.y;
    acc[6] += sv * f3.x; acc[7] += sv * f3.y;
}

__global__ __launch_bounds__(256)
void agg_kernel(const int* __restrict__ offs, const int2* __restrict__ sedge,
                const __half* __restrict__ g, float* __restrict__ out, int n0) {
    int row = blockIdx.x * 8 + (threadIdx.x >> 5);
    if (row >= n0) return;
    int lane = threadIdx.x & 31;
    int hw = lane >> 4;        // half-warp id 0/1
    int hl = lane & 15;        // lane within half-warp
    float acc[8];
#pragma unroll
    for (int j = 0; j < 8; j++) acc[j] = 0.f;
    int s = __ldg(offs + row), e = __ldg(offs + row + 1);
    int i = s + hw;
    for (; i + 2 < e; i += 4) {
        int2 ea = __ldg(sedge + i);
        int2 eb = __ldg(sedge + i + 2);
        gacc16(ea.x, __int_as_float(ea.y), hl, g, acc);
        gacc16(eb.x, __int_as_float(eb.y), hl, g, acc);
    }
    for (; i < e; i += 2) {
        int2 ea = __ldg(sedge + i);
        gacc16(ea.x, __int_as_float(ea.y), hl, g, acc);
    }
#pragma unroll
    for (int j = 0; j < 8; j++) acc[j] += __shfl_down_sync(0xffffffffu, acc[j], 16);
    if (hw == 0) {
        float4* op = (float4*)(out + (size_t)row * D + hl * 8);
        float4 c0 = op[0], c1 = op[1];
        c0.x += acc[0]; c0.y += acc[1]; c0.z += acc[2]; c0.w += acc[3];
        c1.x += acc[4]; c1.y += acc[5]; c1.z += acc[6]; c1.w += acc[7];
        op[0] = c0;
        op[1] = c1;
    }
}

// ---------------- launch ----------------
extern "C" void kernel_launch(void* const* d_in, const int* in_sizes, int n_in,
                              void* d_out, int out_size) {
    const float* x0   = (const float*)d_in[0];
    const float* x1   = (const float*)d_in[1];
    const float* x2   = (const float*)d_in[2];
    const float* W1   = (const float*)d_in[3];
    const float* b1   = (const float*)d_in[4];
    const float* a1w  = (const float*)d_in[5];
    const float* a1b  = (const float*)d_in[6];
    const float* a2w  = (const float*)d_in[7];
    const float* a2b  = (const float*)d_in[8];
    const float* Wagg = (const float*)d_in[9];
    const float* bagg = (const float*)d_in[10];
    const int* ar0 = (const int*)d_in[11];
    const int* ac0 = (const int*)d_in[12];
    const int* ar1 = (const int*)d_in[13];
    const int* ac1 = (const int*)d_in[14];
    const int* ar2 = (const int*)d_in[15];
    const int* ac2 = (const int*)d_in[16];
    float* out = (float*)d_out;

    const int N0 = in_sizes[0] / D;
    const int N1 = in_sizes[1] / D;
    const int N2 = in_sizes[2] / D;
    const int E0 = in_sizes[11];
    const int E1 = in_sizes[13];
    const int E2 = in_sizes[15];

    __half* pg;
    float *pa2, *pa1;
    int *pcnt, *poff, *pcur, *pbsum;
    int2* psedge;
    unsigned char* pwp;
    cudaGetSymbolAddress((void**)&pg, g_gall);
    cudaGetSymbolAddress((void**)&pa2, g_a2all);
    cudaGetSymbolAddress((void**)&pa1, g_a1_0);
    cudaGetSymbolAddress((void**)&pcnt, g_cnt);
    cudaGetSymbolAddress((void**)&poff, g_off);
    cudaGetSymbolAddress((void**)&pcur, g_cur);
    cudaGetSymbolAddress((void**)&psedge, g_sedge);
    cudaGetSymbolAddress((void**)&pwp, g_wprep);
    cudaGetSymbolAddress((void**)&pbsum, g_bsum);

    cudaFuncSetAttribute(node_all, cudaFuncAttributeMaxDynamicSharedMemorySize, SMEM_REQ);

    #define WHI(m) (pwp + (size_t)(m) * 2 * 32768)

    // fork a side stream (binning chain + ds0 scat)
    cudaStream_t s2;
    cudaEvent_t eRoot, eN0, eS0, eBin;
    cudaStreamCreateWithFlags(&s2, cudaStreamNonBlocking);
    cudaEventCreateWithFlags(&eRoot, cudaEventDisableTiming);
    cudaEventCreateWithFlags(&eN0, cudaEventDisableTiming);
    cudaEventCreateWithFlags(&eS0, cudaEventDisableTiming);
    cudaEventCreateWithFlags(&eBin, cudaEventDisableTiming);
    cudaEventRecord(eRoot, 0);
    cudaStreamWaitEvent(s2, eRoot, 0);

    const int ET = E0 + E1 + E2;
    const int NB = (N0 + SCAN_CHUNK - 1) / SCAN_CHUNK;
    const int NB0 = (N0 + 127) / 128;
    const int NB1 = (N1 + 127) / 128;
    const int NB2 = (N2 + 127) / 128;

    // side chain: zero -> hist -> scanA -> scanC
    zero_kernel<<<(N0 + 256) / 256, 256, 0, s2>>>(pcnt, N0 + 1);
    hist_kernel<<<(ET + 255) / 256, 256, 0, s2>>>(ar0, E0, ar1, E1, ar2, E2, pcnt);
    scanA_kernel<<<NB, 1024, 0, s2>>>(pcnt, N0, pbsum);
    scanC_kernel<<<NB, 1024, 0, s2>>>(pcnt, N0, NB, pbsum, poff, pcur);
    cudaEventRecord(eBin, s2);

    // main chain: prep_w -> node(ds0) -> node(ds1+ds2)
    prep_w<<<40, 256>>>(W1, Wagg, pwp);
    node_all<<<NB0, 256, SMEM_REQ>>>(
        x0, x1, x2, N0, N1, N2, NB0, NB1, 0,
        WHI(0), WHI(2), WHI(3), WHI(4), WHI(1),
        b1, a1w, a1b, a2w, a2b, bagg,
        pg, pa1, pa2, out);
    cudaEventRecord(eN0, 0);
    node_all<<<NB1 + NB2, 256, SMEM_REQ>>>(
        x0, x1, x2, N0, N1, N2, NB0, NB1, NB0,
        WHI(0), WHI(2), WHI(3), WHI(4), WHI(1),
        b1, a1w, a1b, a2w, a2b, bagg,
        pg, pa1, pa2, out);

    // side: scat0 (ds0-col edges) after node(ds0), overlaps node(ds1+ds2)
    cudaStreamWaitEvent(s2, eN0, 0);
    scat_kernel<<<(E0 + 255) / 256, 256, 0, s2>>>(
        ar0, ac0, E0, nullptr, nullptr, 0, nullptr, nullptr, 0,
        N0, N0 + N1, pa1, pa2, pcur, psedge);
    cudaEventRecord(eS0, s2);

    // main: scat12 (ds1/ds2-col edges) after node(ds1+ds2) + binning
    cudaStreamWaitEvent(0, eBin, 0);
    scat_kernel<<<(E1 + E2 + 255) / 256, 256>>>(
        nullptr, nullptr, 0, ar1, ac1, E1, ar2, ac2, E2,
        N0, N0 + N1, pa1, pa2, pcur, psedge);

    // agg after both scats
    cudaStreamWaitEvent(0, eS0, 0);
    agg_kernel<<<(N0 + 7) / 8, 256>>>(poff, psedge, pg, out, N0);

    // cleanup only when not capturing (leaks a few streams across the
    // harness's handful of calls; no device memory involved)
    cudaStreamCaptureStatus cst = cudaStreamCaptureStatusNone;
    cudaStreamIsCapturing(0, &cst);
    if (cst == cudaStreamCaptureStatusNone) {
        cudaStreamDestroy(s2);
        cudaEventDestroy(eRoot);
        cudaEventDestroy(eN0);
        cudaEventDestroy(eS0);
        cudaEventDestroy(eBin);
    }
}